// round 8
// baseline (speedup 1.0000x reference)
#include <cuda_runtime.h>

#define L 32768
#define E 1024
#define H 8
#define D 128
#define E4 256            // float4 per row
#define NB 128            // fused blocks (1 wave)
#define RPB 256           // rows per fused block
#define TILE 16
#define NT (RPB/TILE)     // 16 tiles per block
#define RSQRT_D 0.08838834764831845f

typedef unsigned long long u64;

// ---------------- device scratch ----------------
__device__ float g_q[E];
__device__ float g_s[H][E];
__device__ float g_pm[NB * H];
__device__ float g_ps[NB * H];
__device__ float g_partial[NB][H][E];   // 4 MB (unnormalized, local max)
__device__ float g_partial2[16][H][E];  // 512 KB
__device__ float g_w[H][E];
__device__ float g_attn[E];

#define FMA2(d, a, b, c) \
    asm("fma.rn.f32x2 %0, %1, %2, %3;" : "=l"(d) : "l"(a), "l"(b), "l"(c))
#define ADD2(d, a, b) \
    asm("add.rn.f32x2 %0, %1, %2;" : "=l"(d) : "l"(a), "l"(b))

__device__ __forceinline__ u64 pack2(float a, float b) {
    u64 u; asm("mov.b64 %0, {%1, %2};" : "=l"(u) : "f"(a), "f"(b)); return u;
}
__device__ __forceinline__ void unpack2(u64 u, float& lo, float& hi) {
    asm("mov.b64 {%0, %1}, %2;" : "=f"(lo), "=f"(hi) : "l"(u));
}
__device__ __forceinline__ float warp_sum(float v) {
    v += __shfl_xor_sync(0xffffffffu, v, 16);
    v += __shfl_xor_sync(0xffffffffu, v, 8);
    v += __shfl_xor_sync(0xffffffffu, v, 4);
    v += __shfl_xor_sync(0xffffffffu, v, 2);
    v += __shfl_xor_sync(0xffffffffu, v, 1);
    return v;
}
__device__ __forceinline__ u64 warp_sum2(u64 v) {
    #pragma unroll
    for (int off = 16; off; off >>= 1) {
        u64 o = __shfl_xor_sync(0xffffffffu, v, off);
        ADD2(v, v, o);
    }
    return v;
}

// ---------------- K1: q = Wq·x0 + bq ----------------
__global__ __launch_bounds__(256) void k_qproj(const float4* __restrict__ W4,
                                               const float4* __restrict__ X4,
                                               const float* __restrict__ bias) {
    int warp = threadIdx.x >> 5, lane = threadIdx.x & 31;
    int row = blockIdx.x * 8 + warp;
    const float4* wr = W4 + (size_t)row * E4;
    float4 a = make_float4(0.f, 0.f, 0.f, 0.f);
    #pragma unroll
    for (int i = 0; i < 8; i++) {
        float4 w = wr[lane + 32 * i];
        float4 x = X4[lane + 32 * i];
        a.x = fmaf(w.x, x.x, a.x); a.y = fmaf(w.y, x.y, a.y);
        a.z = fmaf(w.z, x.z, a.z); a.w = fmaf(w.w, x.w, a.w);
    }
    float acc = warp_sum((a.x + a.y) + (a.z + a.w));
    if (lane == 0) g_q[row] = acc + bias[row];
}

// ---------------- K2: s[h] = rsqrtD * Wk_h^T q_h (d-split, MLP-8) -------
__global__ __launch_bounds__(256) void k_sproj(const float4* __restrict__ W4) {
    int h = blockIdx.x >> 2, seg = blockIdx.x & 3;
    int t = threadIdx.x;
    int dq = t >> 6, ec = t & 63;
    int e4 = seg * 64 + ec;
    __shared__ float qsh[D];
    __shared__ float4 pacc[4][64];
    if (t < D) qsh[t] = g_q[h * D + t];
    __syncthreads();
    const float4* Wk = W4 + (size_t)(E + h * D + dq * 32) * E4 + e4;
    float4 a = make_float4(0.f, 0.f, 0.f, 0.f);
    #pragma unroll 8
    for (int d = 0; d < 32; d++) {
        float4 w = Wk[(size_t)d * E4];
        float q = qsh[dq * 32 + d];
        a.x = fmaf(w.x, q, a.x); a.y = fmaf(w.y, q, a.y);
        a.z = fmaf(w.z, q, a.z); a.w = fmaf(w.w, q, a.w);
    }
    pacc[dq][ec] = a;
    __syncthreads();
    if (t < 64) {
        float4 r = pacc[0][t];
        #pragma unroll
        for (int k = 1; k < 4; k++) {
            float4 v = pacc[k][t];
            r.x += v.x; r.y += v.y; r.z += v.z; r.w += v.w;
        }
        r.x *= RSQRT_D; r.y *= RSQRT_D; r.z *= RSQRT_D; r.w *= RSQRT_D;
        ((float4*)g_s[h])[seg * 64 + t] = r;
    }
}

// ---------------- K3: fused logits + online softmax + weighted sum -------
// 512 threads, 16 warps = 4 column-groups (cg) x 4 row-groups (rg).
struct FSmem {
    float4 xbuf[2][TILE][E4];      // 128 KB double-buffered X tile
    u64 s2sh[4][E4][5];            // 40 KB head-pair-packed s, pad-5 (conflict-free)
    u64 plg[4][TILE][4];           // 2 KB partial logits (head-pair packed)
    u64 a2[TILE][H];               // 1 KB exp weights (e-duplicated)
    float m_run[H], s_run[H], f_sh[H];
};

__device__ __forceinline__ void issue_loads(FSmem* s, int buf,
                                            const float4* __restrict__ X4,
                                            int row_base, int t) {
    #pragma unroll
    for (int i = 0; i < 8; i++) {
        int idx = t + 512 * i;                  // 0..4095
        int row = idx >> 8, col = idx & 255;
        unsigned sa = (unsigned)__cvta_generic_to_shared(&s->xbuf[buf][row][col]);
        const float4* g = X4 + (size_t)(row_base + row) * E4 + col;
        asm volatile("cp.async.cg.shared.global [%0], [%1], 16;"
                     :: "r"(sa), "l"(g) : "memory");
    }
    asm volatile("cp.async.commit_group;" ::: "memory");
}

__global__ __launch_bounds__(512, 1) void k_fused(const float4* __restrict__ X4) {
    extern __shared__ char smem_raw[];
    FSmem* s = reinterpret_cast<FSmem*>(smem_raw);
    int t = threadIdx.x, w = t >> 5, j = t & 31;
    int b = blockIdx.x;
    int row0 = b * RPB;
    int cg = w & 3, rg = w >> 2;

    // prologue: build head-pair-packed s2sh + init stats
    #pragma unroll
    for (int i = 0; i < 8; i++) {
        int idx = t + 512 * i;                  // 0..4095
        int hp = idx & 3, f = (idx >> 2) & 255, k = idx >> 10;
        int e = f * 4 + k;
        s->s2sh[k][f][hp] = pack2(g_s[2 * hp][e], g_s[2 * hp + 1][e]);
    }
    if (t < H) { s->m_run[t] = -1e30f; s->s_run[t] = 0.f; }

    u64 accB[H][2];
    #pragma unroll
    for (int h = 0; h < H; h++) { accB[h][0] = 0ull; accB[h][1] = 0ull; }

    issue_loads(s, 0, X4, row0, t);

    for (int tile = 0; tile < NT; tile++) {
        int buf = tile & 1;
        asm volatile("cp.async.wait_group 0;" ::: "memory");
        __syncthreads();
        if (tile + 1 < NT) issue_loads(s, buf ^ 1, X4, row0 + (tile + 1) * TILE, t);

        // ---- phase A: head-pair-packed partial logits ----
        u64 acc[4][4];                          // [rr][hp]
        #pragma unroll
        for (int rr = 0; rr < 4; rr++)
            #pragma unroll
            for (int hp = 0; hp < 4; hp++) acc[rr][hp] = 0ull;

        #pragma unroll
        for (int cc = 0; cc < 2; cc++) {
            int f = cg * 64 + cc * 32 + j;
            float4 xv[4];
            #pragma unroll
            for (int rr = 0; rr < 4; rr++) xv[rr] = s->xbuf[buf][rg * 4 + rr][f];
            #pragma unroll
            for (int k = 0; k < 4; k++) {
                u64 sk[4];
                #pragma unroll
                for (int hp = 0; hp < 4; hp++) sk[hp] = s->s2sh[k][f][hp];
                #pragma unroll
                for (int rr = 0; rr < 4; rr++) {
                    float xe = (k == 0) ? xv[rr].x : (k == 1) ? xv[rr].y
                             : (k == 2) ? xv[rr].z : xv[rr].w;
                    u64 xd = pack2(xe, xe);
                    #pragma unroll
                    for (int hp = 0; hp < 4; hp++)
                        FMA2(acc[rr][hp], xd, sk[hp], acc[rr][hp]);
                }
            }
        }
        #pragma unroll
        for (int rr = 0; rr < 4; rr++)
            #pragma unroll
            for (int hp = 0; hp < 4; hp++) {
                u64 v = warp_sum2(acc[rr][hp]);
                if (j == 0) s->plg[cg][rg * 4 + rr][hp] = v;
            }
        __syncthreads();

        // ---- stats: single 128-thread warp-parallel section ----
        if (t < 128) {
            int h = t >> 4, r = t & 15, hp = h >> 1;
            u64 z2 = s->plg[0][r][hp];
            ADD2(z2, z2, s->plg[1][r][hp]);
            ADD2(z2, z2, s->plg[2][r][hp]);
            ADD2(z2, z2, s->plg[3][r][hp]);
            float lo, hi; unpack2(z2, lo, hi);
            float z = (h & 1) ? hi : lo;
            float mt = z;
            #pragma unroll
            for (int off = 8; off; off >>= 1)
                mt = fmaxf(mt, __shfl_xor_sync(0xffffffffu, mt, off));
            float m_old = s->m_run[h];
            float m_new = fmaxf(m_old, mt);
            float e = __expf(z - m_new);
            s->a2[r][h] = pack2(e, e);
            float st = e;
            #pragma unroll
            for (int off = 8; off; off >>= 1)
                st += __shfl_xor_sync(0xffffffffu, st, off);
            if (r == 0) {
                float fr = __expf(m_old - m_new);
                s->s_run[h] = s->s_run[h] * fr + st;
                s->m_run[h] = m_new;
                s->f_sh[h] = fr;
            }
        }
        __syncthreads();

        // ---- phase B: rescale + accumulate (512 threads: col x row-half) ----
        int col = t & 255, half = t >> 8, r0 = half * 8;
        #pragma unroll
        for (int h = 0; h < H; h++) {
            float fh = s->f_sh[h];
            u64 f2 = pack2(fh, fh);
            FMA2(accB[h][0], accB[h][0], f2, 0ull);
            FMA2(accB[h][1], accB[h][1], f2, 0ull);
        }
        #pragma unroll
        for (int r = 0; r < 8; r++) {
            ulonglong2 xv = *(const ulonglong2*)&s->xbuf[buf][r0 + r][col];
            const ulonglong2* ap = (const ulonglong2*)s->a2[r0 + r];
            #pragma unroll
            for (int hp = 0; hp < 4; hp++) {
                ulonglong2 aa = ap[hp];
                FMA2(accB[2 * hp][0],     aa.x, xv.x, accB[2 * hp][0]);
                FMA2(accB[2 * hp][1],     aa.x, xv.y, accB[2 * hp][1]);
                FMA2(accB[2 * hp + 1][0], aa.y, xv.x, accB[2 * hp + 1][0]);
                FMA2(accB[2 * hp + 1][1], aa.y, xv.y, accB[2 * hp + 1][1]);
            }
        }
    }

    // ---- merge the two row-halves via SMEM (reuse xbuf), write partials ----
    __syncthreads();
    ulonglong2* mbuf = (ulonglong2*)s->xbuf;    // [H][256]
    int col = t & 255, half = t >> 8;
    if (half == 1) {
        #pragma unroll
        for (int h = 0; h < H; h++) {
            ulonglong2 v; v.x = accB[h][0]; v.y = accB[h][1];
            mbuf[h * 256 + col] = v;
        }
    }
    __syncthreads();
    if (half == 0) {
        #pragma unroll
        for (int h = 0; h < H; h++) {
            ulonglong2 o = mbuf[h * 256 + col];
            ADD2(accB[h][0], accB[h][0], o.x);
            ADD2(accB[h][1], accB[h][1], o.y);
            ulonglong2 v; v.x = accB[h][0]; v.y = accB[h][1];
            ((ulonglong2*)g_partial[b][h])[col] = v;
        }
    }
    if (t < H) { g_pm[b * H + t] = s->m_run[t]; g_ps[b * H + t] = s->s_run[t]; }
}

// ---------------- K4a: rescale + 8-slot group reduce (256 blocks) --------
__global__ __launch_bounds__(128) void k_reduce1() {
    int t = threadIdx.x;
    int out4 = blockIdx.x * 128 + t;            // 0..2047
    int h = blockIdx.x >> 1;                    // uniform per block
    int g = blockIdx.y;                         // 16 groups of 8 slots
    __shared__ float red[4];
    __shared__ float Msh;
    __shared__ float fac[8];

    float m = g_pm[t * H + h];                  // t covers 128 slots
    #pragma unroll
    for (int o = 16; o; o >>= 1) m = fmaxf(m, __shfl_xor_sync(0xffffffffu, m, o));
    if ((t & 31) == 0) red[t >> 5] = m;
    __syncthreads();
    if (t == 0) Msh = fmaxf(fmaxf(red[0], red[1]), fmaxf(red[2], red[3]));
    __syncthreads();
    if (t < 8) fac[t] = __expf(g_pm[(g * 8 + t) * H + h] - Msh);
    __syncthreads();

    const float4* P = (const float4*)g_partial;
    float4 acc = make_float4(0.f, 0.f, 0.f, 0.f);
    #pragma unroll
    for (int k = 0; k < 8; k++) {
        float4 v = P[(size_t)(g * 8 + k) * 2048 + out4];
        float f = fac[k];
        acc.x = fmaf(v.x, f, acc.x); acc.y = fmaf(v.y, f, acc.y);
        acc.z = fmaf(v.z, f, acc.z); acc.w = fmaf(v.w, f, acc.w);
    }
    ((float4*)g_partial2)[(size_t)g * 2048 + out4] = acc;
}

// ---------------- K4b: final sum + 1/S normalize -------------------------
__global__ __launch_bounds__(128) void k_reduce2() {
    int t = threadIdx.x;
    int out4 = blockIdx.x * 128 + t;
    int h = blockIdx.x >> 1;
    __shared__ float red[4];
    __shared__ float Msh, invSsh;

    float m = g_pm[t * H + h];
    #pragma unroll
    for (int o = 16; o; o >>= 1) m = fmaxf(m, __shfl_xor_sync(0xffffffffu, m, o));
    if ((t & 31) == 0) red[t >> 5] = m;
    __syncthreads();
    if (t == 0) Msh = fmaxf(fmaxf(red[0], red[1]), fmaxf(red[2], red[3]));
    __syncthreads();
    float sp = g_ps[t * H + h] * __expf(g_pm[t * H + h] - Msh);
    sp = warp_sum(sp);
    if ((t & 31) == 0) red[t >> 5] = sp;
    __syncthreads();
    if (t == 0) invSsh = 1.0f / (red[0] + red[1] + red[2] + red[3]);
    __syncthreads();
    float invS = invSsh;

    const float4* P = (const float4*)g_partial2;
    float4 acc = make_float4(0.f, 0.f, 0.f, 0.f);
    #pragma unroll
    for (int g = 0; g < 16; g++) {
        float4 v = P[(size_t)g * 2048 + out4];
        acc.x += v.x; acc.y += v.y; acc.z += v.z; acc.w += v.w;
    }
    acc.x *= invS; acc.y *= invS; acc.z *= invS; acc.w *= invS;
    ((float4*)g_w)[out4] = acc;
}

// ---------------- K5: attn = Wv·w + bv ----------------
__global__ __launch_bounds__(256) void k_vproj(const float4* __restrict__ W4,
                                               const float* __restrict__ bias) {
    int warp = threadIdx.x >> 5, lane = threadIdx.x & 31;
    int row = blockIdx.x * 8 + warp;
    int h = row >> 7;
    const float4* wr = W4 + (size_t)(2 * E + row) * E4;
    const float4* v4 = (const float4*)g_w[h];
    float4 a = make_float4(0.f, 0.f, 0.f, 0.f);
    #pragma unroll
    for (int i = 0; i < 8; i++) {
        float4 w = wr[lane + 32 * i];
        float4 x = v4[lane + 32 * i];
        a.x = fmaf(w.x, x.x, a.x); a.y = fmaf(w.y, x.y, a.y);
        a.z = fmaf(w.z, x.z, a.z); a.w = fmaf(w.w, x.w, a.w);
    }
    float acc = warp_sum((a.x + a.y) + (a.z + a.w));
    if (lane == 0) g_attn[row] = acc + bias[2 * E + row];
}

// ---------------- K6: out = Wo·attn + bo ----------------
__global__ __launch_bounds__(256) void k_oproj(const float4* __restrict__ Wo4,
                                               const float* __restrict__ bo,
                                               float* __restrict__ out) {
    int warp = threadIdx.x >> 5, lane = threadIdx.x & 31;
    int row = blockIdx.x * 8 + warp;
    const float4* wr = Wo4 + (size_t)row * E4;
    const float4* v4 = (const float4*)g_attn;
    float4 a = make_float4(0.f, 0.f, 0.f, 0.f);
    #pragma unroll
    for (int i = 0; i < 8; i++) {
        float4 w = wr[lane + 32 * i];
        float4 x = v4[lane + 32 * i];
        a.x = fmaf(w.x, x.x, a.x); a.y = fmaf(w.y, x.y, a.y);
        a.z = fmaf(w.z, x.z, a.z); a.w = fmaf(w.w, x.w, a.w);
    }
    float acc = warp_sum((a.x + a.y) + (a.z + a.w));
    if (lane == 0) out[row] = acc + bo[row];
}

extern "C" void kernel_launch(void* const* d_in, const int* in_sizes, int n_in,
                              void* d_out, int out_size) {
    const float* x   = (const float*)d_in[0];   // [L, E]
    const float* Win = (const float*)d_in[1];   // [3E, E]
    const float* bin = (const float*)d_in[2];   // [3E]
    const float* Wo  = (const float*)d_in[3];   // [E, E]
    const float* bo  = (const float*)d_in[4];   // [E]
    float* out = (float*)d_out;

    const float4* X4   = (const float4*)x;
    const float4* Win4 = (const float4*)Win;
    const float4* Wo4  = (const float4*)Wo;

    static int smem_set = 0;
    if (!smem_set) {
        cudaFuncSetAttribute(k_fused, cudaFuncAttributeMaxDynamicSharedMemorySize,
                             (int)sizeof(FSmem));
        smem_set = 1;
    }

    k_qproj<<<128, 256>>>(Win4, X4, bin);
    k_sproj<<<32, 256>>>(Win4);
    k_fused<<<NB, 512, sizeof(FSmem)>>>(X4);
    k_reduce1<<<dim3(16, 16), 128>>>();
    k_reduce2<<<16, 128>>>();
    k_vproj<<<128, 256>>>(Win4, bin);
    k_oproj<<<128, 256>>>(Wo4, bo, out);
}